// round 4
// baseline (speedup 1.0000x reference)
#include <cuda_runtime.h>
#include <cstdint>

// Problem constants
#define NPTS   131072
#define DIMK   64      // slice width (we use inpt[:, 64:128])
#define KCENT  1024
#define INROW  128     // inpt row stride

// Tiling
#define BM 64
#define BN 128
#define TM 8
#define TN 4
#define THREADS 256

__device__ float g_cnorm[KCENT];

// ---- f32x2 helpers (exact fp32 semantics, 2 FMAs per instruction) ----
__device__ __forceinline__ void fma2(unsigned long long& d,
                                     unsigned long long a,
                                     unsigned long long b) {
    asm("fma.rn.f32x2 %0, %1, %2, %0;" : "+l"(d) : "l"(a), "l"(b));
}
__device__ __forceinline__ float2 unpack2(unsigned long long v) {
    float2 f;
    asm("mov.b64 {%0, %1}, %2;" : "=f"(f.x), "=f"(f.y) : "l"(v));
    return f;
}
// 8-byte shared load straight into a 64-bit register pair (the f32x2 operand)
__device__ __forceinline__ unsigned long long lds64(unsigned addr) {
    unsigned long long r;
    asm volatile("ld.shared.b64 %0, [%1];" : "=l"(r) : "r"(addr));
    return r;
}

// ---- center squared norms ----
__global__ void cnorm_kernel(const float* __restrict__ centers) {
    int n = blockIdx.x * blockDim.x + threadIdx.x;
    if (n < KCENT) {
        const float* c = centers + (size_t)n * DIMK;
        float s = 0.f;
        #pragma unroll
        for (int k = 0; k < DIMK; k++) s = fmaf(c[k], c[k], s);
        g_cnorm[n] = s;
    }
}

// ---- fused GEMM + argmin ----
// Xs: [m][k]      64 x 64 floats (16 KB), a-reads are warp-broadcast
// Cs: pair-interleaved [k/2][n][2] = 32 x 128 x 2 floats (32 KB),
//     b-reads (n = tx + 32j) are LDS.64 at the 2-phase/256B floor.
__global__ __launch_bounds__(THREADS, 2)
void label_kernel(const float* __restrict__ inpt,
                  const float* __restrict__ centers,
                  float* __restrict__ out) {
    __shared__ __align__(16) float Xs[BM * DIMK];           // 4096 floats
    __shared__ __align__(16) float Cs[(DIMK / 2) * BN * 2]; // 8192 floats

    const int tid = threadIdx.x;
    const int ty  = tid >> 5;   // warp id 0..7  -> rows ty*8 .. ty*8+7
    const int tx  = tid & 31;   // lane          -> cols tx + 32*j
    const int m0  = blockIdx.x * BM;
    const int mbase = ty * TM;

    // Load X tile: rows m0..m0+63, cols 64..127 (second slice)
    {
        const int r  = tid >> 4;   // 0..15
        const int kg = tid & 15;   // float4 group within the 64 cols
        #pragma unroll
        for (int rep = 0; rep < 4; rep++) {
            const int m = r + rep * 16;
            float4 v = *reinterpret_cast<const float4*>(
                inpt + (size_t)(m0 + m) * INROW + DIMK + kg * 4);
            float2* p = reinterpret_cast<float2*>(&Xs[m * DIMK + kg * 4]);
            p[0] = make_float2(v.x, v.y);
            p[1] = make_float2(v.z, v.w);
        }
    }

    const unsigned xs_base = (unsigned)__cvta_generic_to_shared(Xs);
    const unsigned cs_base = (unsigned)__cvta_generic_to_shared(Cs);

    float bestd[TM];
    int   bestn[TM];
    #pragma unroll
    for (int i = 0; i < TM; i++) {
        bestd[i] = __int_as_float(0x7f800000);  // +inf sentinel
        bestn[i] = 0;
    }

    for (int n0 = 0; n0 < KCENT; n0 += BN) {
        __syncthreads();
        // Load C tile, pair-interleaved on k
        {
            const int n = tid >> 1;       // 0..127
            const int h = tid & 1;        // which half of k
            const float* src = centers + (size_t)(n0 + n) * DIMK + h * 32;
            #pragma unroll
            for (int i4 = 0; i4 < 8; i4++) {
                float4 v = *reinterpret_cast<const float4*>(src + i4 * 4);
                const int k = h * 32 + i4 * 4;
                *reinterpret_cast<float2*>(&Cs[(k >> 1) * (BN * 2) + 2 * n])
                    = make_float2(v.x, v.y);
                *reinterpret_cast<float2*>(&Cs[((k >> 1) + 1) * (BN * 2) + 2 * n])
                    = make_float2(v.z, v.w);
            }
        }
        __syncthreads();

        // acc[i][j] packs (sum over even k, sum over odd k)
        unsigned long long acc[TM][TN];
        #pragma unroll
        for (int i = 0; i < TM; i++)
            #pragma unroll
            for (int j = 0; j < TN; j++) acc[i][j] = 0ull;

        #pragma unroll 4
        for (int kk = 0; kk < DIMK / 2; kk++) {
            unsigned long long b[TN];
            #pragma unroll
            for (int j = 0; j < TN; j++)
                b[j] = lds64(cs_base +
                             (unsigned)((kk * (BN * 2) + 2 * (tx + 32 * j)) * 4));
            unsigned long long a[TM];
            #pragma unroll
            for (int i = 0; i < TM; i++)
                a[i] = lds64(xs_base +
                             (unsigned)(((mbase + i) * DIMK + 2 * kk) * 4));
            #pragma unroll
            for (int i = 0; i < TM; i++)
                #pragma unroll
                for (int j = 0; j < TN; j++)
                    fma2(acc[i][j], a[i], b[j]);
        }

        // Epilogue: d = ||c||^2 - 2*dot, running argmin (ascending n keeps
        // first-minimum semantics of jnp.argmin)
        float cn[TN];
        #pragma unroll
        for (int j = 0; j < TN; j++)
            cn[j] = __ldg(&g_cnorm[n0 + tx + 32 * j]);

        #pragma unroll
        for (int i = 0; i < TM; i++) {
            #pragma unroll
            for (int j = 0; j < TN; j++) {
                float2 s = unpack2(acc[i][j]);
                float dot = s.x + s.y;
                float d = fmaf(-2.0f, dot, cn[j]);
                int n = n0 + tx + 32 * j;
                if (d < bestd[i]) { bestd[i] = d; bestn[i] = n; }
            }
        }
    }

    // Warp reduction per row (lanes hold disjoint n-sets); tie -> lower index
    #pragma unroll
    for (int i = 0; i < TM; i++) {
        float d = bestd[i];
        int   n = bestn[i];
        #pragma unroll
        for (int off = 16; off > 0; off >>= 1) {
            float od = __shfl_down_sync(0xffffffffu, d, off);
            int   on = __shfl_down_sync(0xffffffffu, n, off);
            if (od < d || (od == d && on < n)) { d = od; n = on; }
        }
        // Output dtype is float32: labels 0..1023 are exactly representable.
        if (tx == 0) out[m0 + mbase + i] = (float)n;
    }
}

extern "C" void kernel_launch(void* const* d_in, const int* in_sizes, int n_in,
                              void* d_out, int out_size) {
    // Identify inputs by element count (robust to metadata ordering):
    //   inpt:     131072*128 = 16777216 elements (unique)
    //   centers0: 1024*64    = 65536 elements (first  such tensor)
    //   centers1: 1024*64    = 65536 elements (second such tensor)
    const float* inpt     = nullptr;
    const float* centers1 = nullptr;
    int centers_seen = 0;
    for (int i = 0; i < n_in; i++) {
        if (in_sizes[i] == NPTS * INROW) {
            inpt = (const float*)d_in[i];
        } else if (in_sizes[i] == KCENT * DIMK) {
            centers_seen++;
            if (centers_seen == 2) centers1 = (const float*)d_in[i];
        }
    }
    // Fallback to assumed order if sizes didn't disambiguate
    if (!inpt)     inpt     = (const float*)d_in[0];
    if (!centers1) centers1 = (const float*)d_in[n_in - 1];

    float* out = (float*)d_out;

    cnorm_kernel<<<(KCENT + 255) / 256, 256>>>(centers1);
    label_kernel<<<NPTS / BM, THREADS>>>(inpt, centers1, out);
}